// round 2
// baseline (speedup 1.0000x reference)
#include <cuda_runtime.h>
#include <cuda_bf16.h>
#include <mma.h>
#include <cstdint>

using namespace nvcuda;

#define BATCH 2048
#define NIN   2048
#define NG    8192
#define NCOL  16384  // NG*2

// Scratch (static device globals -- allocation-free rule)
__device__ __nv_bfloat16 g_P[(size_t)NIN * NCOL];     // exp(c), 67 MB
__device__ __nv_bfloat16 g_xb[(size_t)BATCH * NIN];   // x in bf16, 8 MB
__device__ float g_spart[16 * NCOL];                  // partial column sums
__device__ float g_rs[NCOL];                          // 1/colsum
__device__ float g_coef[4 * NG];                      // alpha,beta,gamma,delta

// ---------------------------------------------------------------------------
// Kernel 1: x -> bf16
__global__ void k_xcvt(const float* __restrict__ x) {
    int i = blockIdx.x * 256 + threadIdx.x;
    g_xb[i] = __float2bfloat16(x[i]);
}

// ---------------------------------------------------------------------------
// Kernel 2: P = exp(c) (bf16) + partial column sums (fp32).
// grid (64, 16), block 256. Each thread: one column j, 128 rows.
__global__ void k_exp(const float* __restrict__ c) {
    int j = blockIdx.x * 256 + threadIdx.x;
    int i0 = blockIdx.y * 128;
    float s = 0.f;
#pragma unroll 4
    for (int ii = 0; ii < 128; ++ii) {
        size_t idx = (size_t)(i0 + ii) * NCOL + j;
        float e = __expf(c[idx]);
        g_P[idx] = __float2bfloat16(e);
        s += e;
    }
    g_spart[blockIdx.y * NCOL + j] = s;
}

// Kernel 3: reduce partials -> reciprocal column sums
__global__ void k_sred() {
    int j = blockIdx.x * 256 + threadIdx.x;
    float s = 0.f;
#pragma unroll
    for (int cK = 0; cK < 16; ++cK) s += g_spart[cK * NCOL + j];
    g_rs[j] = 1.f / s;
}

// ---------------------------------------------------------------------------
// Kernel 4: per-gate affine coefficients from softmax(w).
// gates are affine in (1, A, B, AB):
//  g0=0, g1=AB, g2=A-AB, g3=A, g4=B-AB, g5=B, g6=A+B-2AB, g7=A+B-AB,
//  g8=1-A-B+AB, g9=1-A-B+2AB, g10=1-B, g11=1-B+AB, g12=1-A, g13=1-A+AB,
//  g14=1-AB, g15=1
__global__ void k_coef(const float* __restrict__ w) {
    int g = blockIdx.x * 256 + threadIdx.x;
    if (g >= NG) return;
    float v[16];
    float m = -1e30f;
#pragma unroll
    for (int k = 0; k < 16; ++k) { v[k] = w[k * NG + g]; m = fmaxf(m, v[k]); }
    float sum = 0.f;
#pragma unroll
    for (int k = 0; k < 16; ++k) { v[k] = __expf(v[k] - m); sum += v[k]; }
    float inv = 1.f / sum;
#pragma unroll
    for (int k = 0; k < 16; ++k) v[k] *= inv;

    float al = v[8]+v[9]+v[10]+v[11]+v[12]+v[13]+v[14]+v[15];
    float be = v[2]+v[3]+v[6]+v[7] - v[8]-v[9]-v[12]-v[13];
    float ga = v[4]+v[5]+v[6]+v[7] - v[8]-v[9]-v[10]-v[11];
    float de = v[1]-v[2]-v[4]-2.f*v[6]-v[7]+v[8]+2.f*v[9]+v[11]+v[13]-v[14];
    g_coef[g]          = al;
    g_coef[NG + g]     = be;
    g_coef[2*NG + g]   = ga;
    g_coef[3*NG + g]   = de;
}

// ---------------------------------------------------------------------------
// Kernel 5: GEMM y = xb @ P (bf16 -> fp32) with fused gate epilogue.
// BM=128, BN=128, BK=64. 256 threads = 8 warps (2 in M x 4 in N),
// warp tile 64x32 = 4x2 wmma 16x16x16 fragments.
#define BM 128
#define BN 128
#define BK 64
#define LDA 72    // 144 B rows (16B multiple)
#define LDB 136   // 272 B rows (16B multiple)

__global__ __launch_bounds__(256) void k_gemm(float* __restrict__ out) {
    __shared__ __align__(16) unsigned char smraw[BM * LDA * 2 + BK * LDB * 2];
    __nv_bfloat16* As = (__nv_bfloat16*)smraw;
    __nv_bfloat16* Bs = (__nv_bfloat16*)(smraw + BM * LDA * 2);

    const int tid = threadIdx.x;
    const int bn = blockIdx.x, bm = blockIdx.y;
    const int w = tid >> 5, lane = tid & 31;
    const int wm = w >> 2, wn = w & 3;

    wmma::fragment<wmma::accumulator, 16, 16, 16, float> acc[4][2];
#pragma unroll
    for (int mi = 0; mi < 4; ++mi)
#pragma unroll
        for (int ni = 0; ni < 2; ++ni)
            wmma::fill_fragment(acc[mi][ni], 0.f);

    for (int k0 = 0; k0 < NIN; k0 += BK) {
        // A tile: 128 rows x 64 cols = 1024 x uint4 (8 bf16 each)
#pragma unroll
        for (int it = 0; it < 4; ++it) {
            int idx = tid + it * 256;
            int r = idx >> 3, cc = idx & 7;
            *(uint4*)(As + r * LDA + cc * 8) =
                *(const uint4*)(g_xb + (size_t)(bm * BM + r) * NIN + k0 + cc * 8);
        }
        // B tile: 64 rows x 128 cols = 1024 x uint4
#pragma unroll
        for (int it = 0; it < 4; ++it) {
            int idx = tid + it * 256;
            int r = idx >> 4, cc = idx & 15;
            *(uint4*)(Bs + r * LDB + cc * 8) =
                *(const uint4*)(g_P + (size_t)(k0 + r) * NCOL + bn * BN + cc * 8);
        }
        __syncthreads();

#pragma unroll
        for (int kk = 0; kk < BK / 16; ++kk) {
            wmma::fragment<wmma::matrix_a, 16, 16, 16, __nv_bfloat16, wmma::row_major> af[4];
            wmma::fragment<wmma::matrix_b, 16, 16, 16, __nv_bfloat16, wmma::row_major> bf[2];
#pragma unroll
            for (int mi = 0; mi < 4; ++mi)
                wmma::load_matrix_sync(af[mi], As + (wm * 64 + mi * 16) * LDA + kk * 16, LDA);
#pragma unroll
            for (int ni = 0; ni < 2; ++ni)
                wmma::load_matrix_sync(bf[ni], Bs + (kk * 16) * LDB + wn * 32 + ni * 16, LDB);
#pragma unroll
            for (int mi = 0; mi < 4; ++mi)
#pragma unroll
                for (int ni = 0; ni < 2; ++ni)
                    wmma::mma_sync(acc[mi][ni], af[mi], bf[ni], acc[mi][ni]);
        }
        __syncthreads();
    }

    // Fused epilogue: A = y[:,2g]/s, B = y[:,2g+1]/s, out = al + be*A + ga*B + de*A*B
    float* epi = ((float*)smraw) + w * 256;  // per-warp 16x16 scratch (1 KB)
#pragma unroll
    for (int mi = 0; mi < 4; ++mi) {
#pragma unroll
        for (int ni = 0; ni < 2; ++ni) {
            __syncwarp();
            wmma::store_matrix_sync(epi, acc[mi][ni], 16, wmma::mem_row_major);
            __syncwarp();
            int coln0 = bn * BN + wn * 32 + ni * 16;  // even
            int g0 = coln0 >> 1;
            int row0 = bm * BM + wm * 64 + mi * 16;
#pragma unroll
            for (int q = 0; q < 4; ++q) {
                int idx = lane + q * 32;     // 0..127
                int r = idx >> 3, p = idx & 7;
                float Av = epi[r * 16 + 2 * p]     * g_rs[coln0 + 2 * p];
                float Bv = epi[r * 16 + 2 * p + 1] * g_rs[coln0 + 2 * p + 1];
                int g = g0 + p;
                float al = g_coef[g];
                float be = g_coef[NG + g];
                float ga = g_coef[2 * NG + g];
                float de = g_coef[3 * NG + g];
                out[(size_t)(row0 + r) * NG + g] = al + be * Av + ga * Bv + de * Av * Bv;
            }
        }
    }
}

// ---------------------------------------------------------------------------
extern "C" void kernel_launch(void* const* d_in, const int* in_sizes, int n_in,
                              void* d_out, int out_size) {
    const float* x = (const float*)d_in[0];  // (2048, 2048)
    const float* w = (const float*)d_in[1];  // (16, 8192)
    const float* c = (const float*)d_in[2];  // (2048, 8192, 2)
    float* out = (float*)d_out;              // (2048, 8192)

    k_xcvt<<<(BATCH * NIN) / 256, 256>>>(x);
    k_coef<<<NG / 256, 256>>>(w);
    k_exp<<<dim3(NCOL / 256, 16), 256>>>(c);
    k_sred<<<NCOL / 256, 256>>>();
    k_gemm<<<dim3(NCOL / BN, BATCH / BM), 256>>>(out);
}

// round 5
// speedup vs baseline: 1.4528x; 1.4528x over previous
#include <cuda_runtime.h>
#include <cuda_bf16.h>
#include <cstdint>

#define BATCH 2048
#define NIN   2048
#define NG    8192
#define NCOL  16384  // NG*2

// ---------------------------------------------------------------------------
// Scratch (static device globals -- allocation-free rule)
__device__ __align__(1024) __nv_bfloat16 g_Pt[(size_t)NCOL * NIN];  // exp(c)^T, 67 MB
__device__ __align__(1024) __nv_bfloat16 g_xb[(size_t)BATCH * NIN]; // x bf16, 8 MB
__device__ float  g_spart[8 * NCOL];
__device__ float  g_rs[NCOL];
__device__ float4 g_coef4[NG];     // (alpha, beta, gamma, delta) per gate

__device__ __forceinline__ uint32_t smem_to_u32(const void* p) {
    uint32_t a;
    asm("{ .reg .u64 t; cvta.to.shared.u64 t, %1; cvt.u32.u64 %0, t; }" : "=r"(a) : "l"(p));
    return a;
}

// ---------------------------------------------------------------------------
// Kernel 1: x -> bf16
__global__ void k_xcvt(const float* __restrict__ x) {
    int i = blockIdx.x * 256 + threadIdx.x;
    g_xb[i] = __float2bfloat16(x[i]);
}

// ---------------------------------------------------------------------------
// Kernel 2: Pt[j, i] = exp(c[i, j]) (bf16, transposed) + partial column sums.
__global__ __launch_bounds__(256) void k_exp_t(const float* __restrict__ c) {
    __shared__ __nv_bfloat16 sm[256][34];
    __shared__ float ssum[8][32];
    const int tj = threadIdx.x & 31;
    const int ti = threadIdx.x >> 5;
    const int j0 = blockIdx.x * 32;
    const int i0 = blockIdx.y * 256;

    float s = 0.f;
#pragma unroll 4
    for (int it = 0; it < 32; ++it) {
        int il = ti + 8 * it;
        float e = __expf(c[(size_t)(i0 + il) * NCOL + j0 + tj]);
        sm[il][tj] = __float2bfloat16(e);
        s += e;
    }
    ssum[ti][tj] = s;
    __syncthreads();
    if (ti == 0) {
        float t = 0.f;
#pragma unroll
        for (int k = 0; k < 8; ++k) t += ssum[k][tj];
        g_spart[blockIdx.y * NCOL + j0 + tj] = t;
    }
#pragma unroll 4
    for (int jj = 0; jj < 32; ++jj) {
        g_Pt[(size_t)(j0 + jj) * NIN + i0 + threadIdx.x] = sm[threadIdx.x][jj];
    }
}

// Kernel 3: reduce partials -> reciprocal column sums
__global__ void k_sred() {
    int j = blockIdx.x * 256 + threadIdx.x;
    float s = 0.f;
#pragma unroll
    for (int k = 0; k < 8; ++k) s += g_spart[k * NCOL + j];
    g_rs[j] = 1.f / s;
}

// ---------------------------------------------------------------------------
// Kernel 4: per-gate affine coefficients from softmax(w).
__global__ void k_coef(const float* __restrict__ w) {
    int g = blockIdx.x * 256 + threadIdx.x;
    if (g >= NG) return;
    float v[16];
    float m = -1e30f;
#pragma unroll
    for (int k = 0; k < 16; ++k) { v[k] = w[k * NG + g]; m = fmaxf(m, v[k]); }
    float sum = 0.f;
#pragma unroll
    for (int k = 0; k < 16; ++k) { v[k] = __expf(v[k] - m); sum += v[k]; }
    float inv = 1.f / sum;
#pragma unroll
    for (int k = 0; k < 16; ++k) v[k] *= inv;

    float al = v[8]+v[9]+v[10]+v[11]+v[12]+v[13]+v[14]+v[15];
    float be = v[2]+v[3]+v[6]+v[7] - v[8]-v[9]-v[12]-v[13];
    float ga = v[4]+v[5]+v[6]+v[7] - v[8]-v[9]-v[10]-v[11];
    float de = v[1]-v[2]-v[4]-2.f*v[6]-v[7]+v[8]+2.f*v[9]+v[11]+v[13]-v[14];
    g_coef4[g] = make_float4(al, be, ga, de);
}

// ---------------------------------------------------------------------------
// Kernel 5: mma.sync bf16 GEMM  y = xb @ Pt^T  with fused gate epilogue.
// CTA tile 128x256, BK=32, 4-stage cp.async pipeline, 256 threads = 8 warps
// (2 in M x 4 in N), warp tile 64x64.
#define BM 128
#define BN 256
#define BK 32
#define STAGES 4
#define LDSB 80                       // smem row stride in bytes (40 bf16)
#define A_BYTES (BM * LDSB)           // 10240
#define B_BYTES (BN * LDSB)           // 20480
#define STG (A_BYTES + B_BYTES)       // 30720
#define DYN_SMEM (STAGES * STG)       // 122880
#define NKT (NIN / BK)                // 64

#define CP_ASYNC(dst, src) \
    asm volatile("cp.async.cg.shared.global [%0], [%1], 16;" :: "r"(dst), "l"(src) : "memory")
#define CP_COMMIT() asm volatile("cp.async.commit_group;" ::: "memory")
#define CP_WAIT2()  asm volatile("cp.async.wait_group 2;" ::: "memory")

__device__ __forceinline__ void ldsm4(uint32_t& r0, uint32_t& r1, uint32_t& r2, uint32_t& r3, uint32_t a) {
    asm volatile("ldmatrix.sync.aligned.m8n8.x4.shared.b16 {%0,%1,%2,%3}, [%4];"
                 : "=r"(r0), "=r"(r1), "=r"(r2), "=r"(r3) : "r"(a));
}
__device__ __forceinline__ void mma16816(float* d, uint32_t a0, uint32_t a1, uint32_t a2, uint32_t a3,
                                         uint32_t b0, uint32_t b1) {
    asm volatile("mma.sync.aligned.m16n8k16.row.col.f32.bf16.bf16.f32 "
                 "{%0,%1,%2,%3}, {%4,%5,%6,%7}, {%8,%9}, {%0,%1,%2,%3};"
                 : "+f"(d[0]), "+f"(d[1]), "+f"(d[2]), "+f"(d[3])
                 : "r"(a0), "r"(a1), "r"(a2), "r"(a3), "r"(b0), "r"(b1));
}

__global__ __launch_bounds__(256, 1) void k_gemm(float* __restrict__ out) {
    extern __shared__ __align__(128) unsigned char dynsm[];
    const uint32_t sbase = smem_to_u32(dynsm);

    const int tid = threadIdx.x;
    const int wid = tid >> 5, lane = tid & 31;
    const int wm = wid >> 2, wn = wid & 3;
    const int bn = blockIdx.x, bm = blockIdx.y;

    // load mapping: A 512 chunks of 16B (2/thread), B 1024 chunks (4/thread)
    const int ar = tid >> 2, ac = tid & 3;   // A: rows ar, ar+64
    const __nv_bfloat16* gA = g_xb + (size_t)(bm * BM + ar) * NIN + ac * 8;
    const __nv_bfloat16* gB = g_Pt + (size_t)(bn * BN + ar) * NIN + ac * 8;

    float acc[4][8][4];
#pragma unroll
    for (int mi = 0; mi < 4; ++mi)
#pragma unroll
        for (int ni = 0; ni < 8; ++ni)
#pragma unroll
            for (int q = 0; q < 4; ++q) acc[mi][ni][q] = 0.f;

    auto load_stage = [&](int s, int t) {
        const uint32_t sa = sbase + s * STG;
        const uint32_t sb = sa + A_BYTES;
        const int koff = t * BK;
#pragma unroll
        for (int i = 0; i < 2; ++i)
            CP_ASYNC(sa + (ar + i * 64) * LDSB + ac * 16, gA + (size_t)(i * 64) * NIN + koff);
#pragma unroll
        for (int i = 0; i < 4; ++i)
            CP_ASYNC(sb + (ar + i * 64) * LDSB + ac * 16, gB + (size_t)(i * 64) * NIN + koff);
    };

#pragma unroll
    for (int s = 0; s < STAGES - 1; ++s) { load_stage(s, s); CP_COMMIT(); }
    CP_WAIT2();
    __syncthreads();

    // ldmatrix lane addressing (bytes)
    const uint32_t aLaneOff = (uint32_t)((lane & 15) * LDSB + (lane >> 4) * 16);
    const uint32_t bLaneOff = (uint32_t)(((lane & 7) + ((lane >> 4) << 3)) * LDSB + ((lane >> 3) & 1) * 16);

    for (int t = 0; t < NKT; ++t) {
        if (t + STAGES - 1 < NKT) load_stage((t + STAGES - 1) % STAGES, t + STAGES - 1);
        CP_COMMIT();

        const uint32_t sa = sbase + (t % STAGES) * STG + (uint32_t)(wm * 64) * LDSB;
        const uint32_t sb = sbase + (t % STAGES) * STG + A_BYTES + (uint32_t)(wn * 64) * LDSB;

#pragma unroll
        for (int kk = 0; kk < 2; ++kk) {
            uint32_t a[4][4], b[4][4];
#pragma unroll
            for (int mi = 0; mi < 4; ++mi)
                ldsm4(a[mi][0], a[mi][1], a[mi][2], a[mi][3],
                      sa + (uint32_t)(mi * 16) * LDSB + kk * 32 + aLaneOff);
#pragma unroll
            for (int nj = 0; nj < 4; ++nj)
                ldsm4(b[nj][0], b[nj][1], b[nj][2], b[nj][3],
                      sb + (uint32_t)(nj * 16) * LDSB + kk * 32 + bLaneOff);
#pragma unroll
            for (int mi = 0; mi < 4; ++mi)
#pragma unroll
                for (int nj = 0; nj < 4; ++nj) {
                    mma16816(acc[mi][2 * nj],     a[mi][0], a[mi][1], a[mi][2], a[mi][3], b[nj][0], b[nj][1]);
                    mma16816(acc[mi][2 * nj + 1], a[mi][0], a[mi][1], a[mi][2], a[mi][3], b[nj][2], b[nj][3]);
                }
        }
        CP_WAIT2();
        __syncthreads();
    }

    // ------------------------------------------------------------------
    // Epilogue in registers. D frag: d0,d1 = (row lane>>2, cols (lane&3)*2 +{0,1}),
    // d2,d3 = (row+8, same cols). Even col = A, odd col = B of gate g.
    const int row0 = bm * BM + wm * 64 + (lane >> 2);
    const int gbase = bn * (BN / 2) + wn * 32 + (lane & 3);
#pragma unroll
    for (int ni = 0; ni < 8; ++ni) {
        const int g = gbase + ni * 4;
        const float2 rsv = *(const float2*)(g_rs + 2 * g);
        const float4 cf = g_coef4[g];
#pragma unroll
        for (int mi = 0; mi < 4; ++mi) {
            const float* d = acc[mi][ni];
            float Av = d[0] * rsv.x, Bv = d[1] * rsv.y;
            out[(size_t)(row0 + mi * 16) * NG + g] =
                cf.x + cf.y * Av + cf.z * Bv + cf.w * (Av * Bv);
            Av = d[2] * rsv.x; Bv = d[3] * rsv.y;
            out[(size_t)(row0 + mi * 16 + 8) * NG + g] =
                cf.x + cf.y * Av + cf.z * Bv + cf.w * (Av * Bv);
        }
    }
}

// ---------------------------------------------------------------------------
extern "C" void kernel_launch(void* const* d_in, const int* in_sizes, int n_in,
                              void* d_out, int out_size) {
    const float* x = (const float*)d_in[0];  // (2048, 2048)
    const float* w = (const float*)d_in[1];  // (16, 8192)
    const float* c = (const float*)d_in[2];  // (2048, 8192, 2)
    float* out = (float*)d_out;              // (2048, 8192)

    cudaFuncSetAttribute(k_gemm, cudaFuncAttributeMaxDynamicSharedMemorySize, DYN_SMEM);

    k_xcvt<<<(BATCH * NIN) / 256, 256>>>(x);
    k_coef<<<NG / 256, 256>>>(w);
    k_exp_t<<<dim3(NCOL / 32, NIN / 256), 256>>>(c);
    k_sred<<<NCOL / 256, 256>>>();
    k_gemm<<<dim3(NCOL / BN, BATCH / BM), 256, DYN_SMEM>>>(out);
}

// round 6
// speedup vs baseline: 1.7067x; 1.1748x over previous
#include <cuda_runtime.h>
#include <cuda_bf16.h>
#include <cstdint>

#define BATCH 2048
#define NIN   2048
#define NG    8192
#define NCOL  16384  // NG*2

// ---------------------------------------------------------------------------
// Scratch (static device globals -- allocation-free rule)
__device__ __align__(1024) __nv_bfloat16 g_Pt[(size_t)NCOL * NIN];  // exp(c)^T, 67 MB
__device__ __align__(1024) __nv_bfloat16 g_xb[(size_t)BATCH * NIN]; // x bf16, 8 MB
__device__ float  g_spart[8 * NCOL];
__device__ float4 g_coef4[NG];     // (alpha, beta, gamma, delta) per gate

__device__ __forceinline__ uint32_t smem_to_u32(const void* p) {
    uint32_t a;
    asm("{ .reg .u64 t; cvta.to.shared.u64 t, %1; cvt.u32.u64 %0, t; }" : "=r"(a) : "l"(p));
    return a;
}

// ---------------------------------------------------------------------------
// Kernel 1: fused x->bf16 cast + gate coefficient precompute.
// Blocks [0, 16384): xcvt. Blocks [16384, 16416): coef.
__global__ __launch_bounds__(256) void k_prep(const float* __restrict__ x,
                                              const float* __restrict__ w) {
    int b = blockIdx.x;
    if (b < (BATCH * NIN) / 256) {
        int i = b * 256 + threadIdx.x;
        g_xb[i] = __float2bfloat16(x[i]);
        return;
    }
    int g = (b - (BATCH * NIN) / 256) * 256 + threadIdx.x;
    if (g >= NG) return;
    float v[16];
    float m = -1e30f;
#pragma unroll
    for (int k = 0; k < 16; ++k) { v[k] = w[k * NG + g]; m = fmaxf(m, v[k]); }
    float sum = 0.f;
#pragma unroll
    for (int k = 0; k < 16; ++k) { v[k] = __expf(v[k] - m); sum += v[k]; }
    float inv = 1.f / sum;
#pragma unroll
    for (int k = 0; k < 16; ++k) v[k] *= inv;

    float al = v[8]+v[9]+v[10]+v[11]+v[12]+v[13]+v[14]+v[15];
    float be = v[2]+v[3]+v[6]+v[7] - v[8]-v[9]-v[12]-v[13];
    float ga = v[4]+v[5]+v[6]+v[7] - v[8]-v[9]-v[10]-v[11];
    float de = v[1]-v[2]-v[4]-2.f*v[6]-v[7]+v[8]+2.f*v[9]+v[11]+v[13]-v[14];
    g_coef4[g] = make_float4(al, be, ga, de);
}

// ---------------------------------------------------------------------------
// Kernel 2: Pt[j, i] = exp(c[i, j]) (bf16, transposed) + partial column sums.
__global__ __launch_bounds__(256) void k_exp_t(const float* __restrict__ c) {
    __shared__ __nv_bfloat16 sm[256][34];
    __shared__ float ssum[8][32];
    const int tj = threadIdx.x & 31;
    const int ti = threadIdx.x >> 5;
    const int j0 = blockIdx.x * 32;
    const int i0 = blockIdx.y * 256;

    float s = 0.f;
#pragma unroll 4
    for (int it = 0; it < 32; ++it) {
        int il = ti + 8 * it;
        float e = __expf(c[(size_t)(i0 + il) * NCOL + j0 + tj]);
        sm[il][tj] = __float2bfloat16(e);
        s += e;
    }
    ssum[ti][tj] = s;
    __syncthreads();
    if (ti == 0) {
        float t = 0.f;
#pragma unroll
        for (int k = 0; k < 8; ++k) t += ssum[k][tj];
        g_spart[blockIdx.y * NCOL + j0 + tj] = t;
    }
#pragma unroll 4
    for (int jj = 0; jj < 32; ++jj) {
        g_Pt[(size_t)(j0 + jj) * NIN + i0 + threadIdx.x] = sm[threadIdx.x][jj];
    }
}

// ---------------------------------------------------------------------------
// Kernel 3: mma.sync bf16 GEMM  y = xb @ Pt^T  with fused gate epilogue.
// CTA tile 128x256, BK=32, 4-stage cp.async pipeline, 256 threads = 8 warps
// (2 in M x 4 in N), warp tile 64x64. Column-sum reduction folded into epilogue.
#define BM 128
#define BN 256
#define BK 32
#define STAGES 4
#define LDSB 80                       // smem row stride in bytes (40 bf16)
#define A_BYTES (BM * LDSB)           // 10240
#define B_BYTES (BN * LDSB)           // 20480
#define STG (A_BYTES + B_BYTES)       // 30720
#define DYN_SMEM (STAGES * STG)       // 122880
#define NKT (NIN / BK)                // 64

#define CP_ASYNC(dst, src) \
    asm volatile("cp.async.cg.shared.global [%0], [%1], 16;" :: "r"(dst), "l"(src) : "memory")
#define CP_COMMIT() asm volatile("cp.async.commit_group;" ::: "memory")
#define CP_WAIT2()  asm volatile("cp.async.wait_group 2;" ::: "memory")
#define CP_WAIT0()  asm volatile("cp.async.wait_group 0;" ::: "memory")

__device__ __forceinline__ void ldsm4(uint32_t& r0, uint32_t& r1, uint32_t& r2, uint32_t& r3, uint32_t a) {
    asm volatile("ldmatrix.sync.aligned.m8n8.x4.shared.b16 {%0,%1,%2,%3}, [%4];"
                 : "=r"(r0), "=r"(r1), "=r"(r2), "=r"(r3) : "r"(a));
}
__device__ __forceinline__ void mma16816(float* d, uint32_t a0, uint32_t a1, uint32_t a2, uint32_t a3,
                                         uint32_t b0, uint32_t b1) {
    asm volatile("mma.sync.aligned.m16n8k16.row.col.f32.bf16.bf16.f32 "
                 "{%0,%1,%2,%3}, {%4,%5,%6,%7}, {%8,%9}, {%0,%1,%2,%3};"
                 : "+f"(d[0]), "+f"(d[1]), "+f"(d[2]), "+f"(d[3])
                 : "r"(a0), "r"(a1), "r"(a2), "r"(a3), "r"(b0), "r"(b1));
}

__global__ __launch_bounds__(256, 1) void k_gemm(float* __restrict__ out) {
    extern __shared__ __align__(128) unsigned char dynsm[];
    const uint32_t sbase = smem_to_u32(dynsm);

    const int tid = threadIdx.x;
    const int wid = tid >> 5, lane = tid & 31;
    const int wm = wid >> 2, wn = wid & 3;
    const int bn = blockIdx.x, bm = blockIdx.y;

    const int ar = tid >> 2, ac = tid & 3;
    const __nv_bfloat16* gA = g_xb + (size_t)(bm * BM + ar) * NIN + ac * 8;
    const __nv_bfloat16* gB = g_Pt + (size_t)(bn * BN + ar) * NIN + ac * 8;

    float acc[4][8][4];
#pragma unroll
    for (int mi = 0; mi < 4; ++mi)
#pragma unroll
        for (int ni = 0; ni < 8; ++ni)
#pragma unroll
            for (int q = 0; q < 4; ++q) acc[mi][ni][q] = 0.f;

    auto load_stage = [&](int s, int t) {
        const uint32_t sa = sbase + s * STG;
        const uint32_t sb = sa + A_BYTES;
        const int koff = t * BK;
#pragma unroll
        for (int i = 0; i < 2; ++i)
            CP_ASYNC(sa + (ar + i * 64) * LDSB + ac * 16, gA + (size_t)(i * 64) * NIN + koff);
#pragma unroll
        for (int i = 0; i < 4; ++i)
            CP_ASYNC(sb + (ar + i * 64) * LDSB + ac * 16, gB + (size_t)(i * 64) * NIN + koff);
    };

#pragma unroll
    for (int s = 0; s < STAGES - 1; ++s) { load_stage(s, s); CP_COMMIT(); }
    CP_WAIT2();
    __syncthreads();

    const uint32_t aLaneOff = (uint32_t)((lane & 15) * LDSB + (lane >> 4) * 16);
    const uint32_t bLaneOff = (uint32_t)(((lane & 7) + ((lane >> 4) << 3)) * LDSB + ((lane >> 3) & 1) * 16);

#pragma unroll 4
    for (int t = 0; t < NKT; ++t) {
        if (t + STAGES - 1 < NKT) load_stage((t + STAGES - 1) % STAGES, t + STAGES - 1);
        CP_COMMIT();

        const uint32_t sa = sbase + (t % STAGES) * STG + (uint32_t)(wm * 64) * LDSB;
        const uint32_t sb = sbase + (t % STAGES) * STG + A_BYTES + (uint32_t)(wn * 64) * LDSB;

#pragma unroll
        for (int kk = 0; kk < 2; ++kk) {
            uint32_t a[4][4], b[4][4];
#pragma unroll
            for (int mi = 0; mi < 4; ++mi)
                ldsm4(a[mi][0], a[mi][1], a[mi][2], a[mi][3],
                      sa + (uint32_t)(mi * 16) * LDSB + kk * 32 + aLaneOff);
#pragma unroll
            for (int nj = 0; nj < 4; ++nj)
                ldsm4(b[nj][0], b[nj][1], b[nj][2], b[nj][3],
                      sb + (uint32_t)(nj * 16) * LDSB + kk * 32 + bLaneOff);
#pragma unroll
            for (int mi = 0; mi < 4; ++mi)
#pragma unroll
                for (int nj = 0; nj < 4; ++nj) {
                    mma16816(acc[mi][2 * nj],     a[mi][0], a[mi][1], a[mi][2], a[mi][3], b[nj][0], b[nj][1]);
                    mma16816(acc[mi][2 * nj + 1], a[mi][0], a[mi][1], a[mi][2], a[mi][3], b[nj][2], b[nj][3]);
                }
        }
        CP_WAIT2();
        __syncthreads();
    }
    CP_WAIT0();

    // ------------------------------------------------------------------
    // Column reciprocal table: 256 columns for this CTA, reduced from g_spart.
    float* srec = (float*)dynsm;   // stages dead; reuse
    {
        int j = bn * BN + tid;
        float s = 0.f;
#pragma unroll
        for (int k = 0; k < 8; ++k) s += g_spart[k * NCOL + j];
        srec[tid] = 1.f / s;
    }
    __syncthreads();

    // Epilogue in registers. Even col = A, odd col = B of gate g.
    const int row0 = bm * BM + wm * 64 + (lane >> 2);
    const int lg0 = wn * 32 + (lane & 3);          // local gate idx within CTA [0,128)
    const int gbase = bn * (BN / 2) + lg0;
#pragma unroll
    for (int ni = 0; ni < 8; ++ni) {
        const int g = gbase + ni * 4;
        const float2 rsv = *(const float2*)(srec + 2 * (lg0 + ni * 4));
        const float4 cf = g_coef4[g];
#pragma unroll
        for (int mi = 0; mi < 4; ++mi) {
            const float* d = acc[mi][ni];
            float Av = d[0] * rsv.x, Bv = d[1] * rsv.y;
            out[(size_t)(row0 + mi * 16) * NG + g] =
                cf.x + cf.y * Av + cf.z * Bv + cf.w * (Av * Bv);
            Av = d[2] * rsv.x; Bv = d[3] * rsv.y;
            out[(size_t)(row0 + mi * 16 + 8) * NG + g] =
                cf.x + cf.y * Av + cf.z * Bv + cf.w * (Av * Bv);
        }
    }
}

// ---------------------------------------------------------------------------
extern "C" void kernel_launch(void* const* d_in, const int* in_sizes, int n_in,
                              void* d_out, int out_size) {
    const float* x = (const float*)d_in[0];  // (2048, 2048)
    const float* w = (const float*)d_in[1];  // (16, 8192)
    const float* c = (const float*)d_in[2];  // (2048, 8192, 2)
    float* out = (float*)d_out;              // (2048, 8192)

    cudaFuncSetAttribute(k_gemm, cudaFuncAttributeMaxDynamicSharedMemorySize, DYN_SMEM);

    k_prep<<<(BATCH * NIN) / 256 + NG / 256, 256>>>(x, w);
    k_exp_t<<<dim3(NCOL / 32, NIN / 256), 256>>>(c);
    k_gemm<<<dim3(NCOL / BN, BATCH / BM), 256, DYN_SMEM>>>(out);
}

// round 7
// speedup vs baseline: 1.7139x; 1.0042x over previous
#include <cuda_runtime.h>
#include <cuda_bf16.h>
#include <cstdint>

#define BATCH 2048
#define NIN   2048
#define NG    8192
#define NCOL  16384  // NG*2

// ---------------------------------------------------------------------------
// Scratch (static device globals -- allocation-free rule)
__device__ __align__(1024) __nv_bfloat16 g_Pt[(size_t)NCOL * NIN];  // exp(c)^T, 67 MB
__device__ __align__(1024) __nv_bfloat16 g_xb[(size_t)BATCH * NIN]; // x bf16, 8 MB
__device__ float  g_spart[8 * NCOL];
__device__ float  g_rs[NCOL];
__device__ float4 g_coef4[NG];     // (alpha, beta, gamma, delta) per gate

__device__ __forceinline__ uint32_t smem_to_u32(const void* p) {
    uint32_t a;
    asm("{ .reg .u64 t; cvta.to.shared.u64 t, %1; cvt.u32.u64 %0, t; }" : "=r"(a) : "l"(p));
    return a;
}

// ---------------------------------------------------------------------------
// Kernel 1: fused x->bf16 cast + gate coefficient precompute.
__global__ __launch_bounds__(256) void k_prep(const float* __restrict__ x,
                                              const float* __restrict__ w) {
    int b = blockIdx.x;
    if (b < (BATCH * NIN) / 256) {
        int i = b * 256 + threadIdx.x;
        g_xb[i] = __float2bfloat16(x[i]);
        return;
    }
    int g = (b - (BATCH * NIN) / 256) * 256 + threadIdx.x;
    if (g >= NG) return;
    float v[16];
    float m = -1e30f;
#pragma unroll
    for (int k = 0; k < 16; ++k) { v[k] = w[k * NG + g]; m = fmaxf(m, v[k]); }
    float sum = 0.f;
#pragma unroll
    for (int k = 0; k < 16; ++k) { v[k] = __expf(v[k] - m); sum += v[k]; }
    float inv = 1.f / sum;
#pragma unroll
    for (int k = 0; k < 16; ++k) v[k] *= inv;

    float al = v[8]+v[9]+v[10]+v[11]+v[12]+v[13]+v[14]+v[15];
    float be = v[2]+v[3]+v[6]+v[7] - v[8]-v[9]-v[12]-v[13];
    float ga = v[4]+v[5]+v[6]+v[7] - v[8]-v[9]-v[10]-v[11];
    float de = v[1]-v[2]-v[4]-2.f*v[6]-v[7]+v[8]+2.f*v[9]+v[11]+v[13]-v[14];
    g_coef4[g] = make_float4(al, be, ga, de);
}

// ---------------------------------------------------------------------------
// Kernel 2: Pt[j, i] = exp(c[i, j]) (bf16, transposed) + partial column sums.
__global__ __launch_bounds__(256) void k_exp_t(const float* __restrict__ c) {
    __shared__ __nv_bfloat16 sm[256][34];
    __shared__ float ssum[8][32];
    const int tj = threadIdx.x & 31;
    const int ti = threadIdx.x >> 5;
    const int j0 = blockIdx.x * 32;
    const int i0 = blockIdx.y * 256;

    float s = 0.f;
#pragma unroll 4
    for (int it = 0; it < 32; ++it) {
        int il = ti + 8 * it;
        float e = __expf(c[(size_t)(i0 + il) * NCOL + j0 + tj]);
        sm[il][tj] = __float2bfloat16(e);
        s += e;
    }
    ssum[ti][tj] = s;
    __syncthreads();
    if (ti == 0) {
        float t = 0.f;
#pragma unroll
        for (int k = 0; k < 8; ++k) t += ssum[k][tj];
        g_spart[blockIdx.y * NCOL + j0 + tj] = t;
    }
#pragma unroll 4
    for (int jj = 0; jj < 32; ++jj) {
        g_Pt[(size_t)(j0 + jj) * NIN + i0 + threadIdx.x] = sm[threadIdx.x][jj];
    }
}

// Kernel 3: reduce partials -> reciprocal column sums
__global__ void k_rs() {
    int j = blockIdx.x * 256 + threadIdx.x;
    float s = 0.f;
#pragma unroll
    for (int k = 0; k < 8; ++k) s += g_spart[k * NCOL + j];
    g_rs[j] = 1.f / s;
}

// ---------------------------------------------------------------------------
// Kernel 4: mma.sync bf16 GEMM  y = xb @ Pt^T  with fused gate epilogue.
// CTA tile 128x256, BK=32, 4-stage cp.async pipeline, 512 threads = 16 warps
// (4 in M x 4 in N), warp tile 32x64. 4 warps/SMSP for latency hiding.
#define BM 128
#define BN 256
#define BK 32
#define STAGES 4
#define LDSB 80                       // smem row stride in bytes (40 bf16)
#define A_BYTES (BM * LDSB)           // 10240
#define B_BYTES (BN * LDSB)           // 20480
#define STG (A_BYTES + B_BYTES)       // 30720
#define DYN_SMEM (STAGES * STG)       // 122880
#define NKT (NIN / BK)                // 64

#define CP_ASYNC(dst, src) \
    asm volatile("cp.async.cg.shared.global [%0], [%1], 16;" :: "r"(dst), "l"(src) : "memory")
#define CP_COMMIT() asm volatile("cp.async.commit_group;" ::: "memory")
#define CP_WAIT2()  asm volatile("cp.async.wait_group 2;" ::: "memory")

__device__ __forceinline__ void ldsm4(uint32_t& r0, uint32_t& r1, uint32_t& r2, uint32_t& r3, uint32_t a) {
    asm volatile("ldmatrix.sync.aligned.m8n8.x4.shared.b16 {%0,%1,%2,%3}, [%4];"
                 : "=r"(r0), "=r"(r1), "=r"(r2), "=r"(r3) : "r"(a));
}
__device__ __forceinline__ void mma16816(float* d, uint32_t a0, uint32_t a1, uint32_t a2, uint32_t a3,
                                         uint32_t b0, uint32_t b1) {
    asm volatile("mma.sync.aligned.m16n8k16.row.col.f32.bf16.bf16.f32 "
                 "{%0,%1,%2,%3}, {%4,%5,%6,%7}, {%8,%9}, {%0,%1,%2,%3};"
                 : "+f"(d[0]), "+f"(d[1]), "+f"(d[2]), "+f"(d[3])
                 : "r"(a0), "r"(a1), "r"(a2), "r"(a3), "r"(b0), "r"(b1));
}

__global__ __launch_bounds__(512, 1) void k_gemm(float* __restrict__ out) {
    extern __shared__ __align__(128) unsigned char dynsm[];
    const uint32_t sbase = smem_to_u32(dynsm);

    const int tid = threadIdx.x;
    const int wid = tid >> 5, lane = tid & 31;
    const int wm = wid >> 2, wn = wid & 3;      // 4x4 warp grid
    const int bn = blockIdx.x, bm = blockIdx.y;

    // load mapping: A 640 chunks of 16B (1/thread + rows ar), B 2/thread
    const int ar = tid >> 2, ac = tid & 3;       // ar 0..127, ac 0..3 (x8 bf16)
    const __nv_bfloat16* gA = g_xb + (size_t)(bm * BM + ar) * NIN + ac * 8;
    const __nv_bfloat16* gB = g_Pt + (size_t)(bn * BN + ar) * NIN + ac * 8;

    float acc[2][8][4];
#pragma unroll
    for (int mi = 0; mi < 2; ++mi)
#pragma unroll
        for (int ni = 0; ni < 8; ++ni)
#pragma unroll
            for (int q = 0; q < 4; ++q) acc[mi][ni][q] = 0.f;

    auto load_stage = [&](int s, int t) {
        const uint32_t sa = sbase + s * STG;
        const uint32_t sb = sa + A_BYTES;
        const int koff = t * BK;
        CP_ASYNC(sa + ar * LDSB + ac * 16, gA + koff);
#pragma unroll
        for (int i = 0; i < 2; ++i)
            CP_ASYNC(sb + (ar + i * 128) * LDSB + ac * 16, gB + (size_t)(i * 128) * NIN + koff);
    };

#pragma unroll
    for (int s = 0; s < STAGES - 1; ++s) { load_stage(s, s); CP_COMMIT(); }
    CP_WAIT2();
    __syncthreads();

    const uint32_t aLaneOff = (uint32_t)((lane & 15) * LDSB + (lane >> 4) * 16);
    const uint32_t bLaneOff = (uint32_t)(((lane & 7) + ((lane >> 4) << 3)) * LDSB + ((lane >> 3) & 1) * 16);

#pragma unroll 4
    for (int t = 0; t < NKT; ++t) {
        if (t + STAGES - 1 < NKT) load_stage((t + STAGES - 1) % STAGES, t + STAGES - 1);
        CP_COMMIT();

        const uint32_t sa = sbase + (t % STAGES) * STG + (uint32_t)(wm * 32) * LDSB;
        const uint32_t sb = sbase + (t % STAGES) * STG + A_BYTES + (uint32_t)(wn * 64) * LDSB;

#pragma unroll
        for (int kk = 0; kk < 2; ++kk) {
            uint32_t a[2][4], b[4][4];
#pragma unroll
            for (int mi = 0; mi < 2; ++mi)
                ldsm4(a[mi][0], a[mi][1], a[mi][2], a[mi][3],
                      sa + (uint32_t)(mi * 16) * LDSB + kk * 32 + aLaneOff);
#pragma unroll
            for (int nj = 0; nj < 4; ++nj)
                ldsm4(b[nj][0], b[nj][1], b[nj][2], b[nj][3],
                      sb + (uint32_t)(nj * 16) * LDSB + kk * 32 + bLaneOff);
#pragma unroll
            for (int mi = 0; mi < 2; ++mi)
#pragma unroll
                for (int nj = 0; nj < 4; ++nj) {
                    mma16816(acc[mi][2 * nj],     a[mi][0], a[mi][1], a[mi][2], a[mi][3], b[nj][0], b[nj][1]);
                    mma16816(acc[mi][2 * nj + 1], a[mi][0], a[mi][1], a[mi][2], a[mi][3], b[nj][2], b[nj][3]);
                }
        }
        CP_WAIT2();
        __syncthreads();
    }

    // ------------------------------------------------------------------
    // Epilogue in registers. Even col = A, odd col = B of gate g.
    const int row0 = bm * BM + wm * 32 + (lane >> 2);
    const int gbase = bn * (BN / 2) + wn * 32 + (lane & 3);
#pragma unroll
    for (int ni = 0; ni < 8; ++ni) {
        const int g = gbase + ni * 4;
        const float2 rsv = *(const float2*)(g_rs + 2 * g);
        const float4 cf = g_coef4[g];
#pragma unroll
        for (int mi = 0; mi < 2; ++mi) {
            const float* d = acc[mi][ni];
            float Av = d[0] * rsv.x, Bv = d[1] * rsv.y;
            out[(size_t)(row0 + mi * 16) * NG + g] =
                cf.x + cf.y * Av + cf.z * Bv + cf.w * (Av * Bv);
            Av = d[2] * rsv.x; Bv = d[3] * rsv.y;
            out[(size_t)(row0 + mi * 16 + 8) * NG + g] =
                cf.x + cf.y * Av + cf.z * Bv + cf.w * (Av * Bv);
        }
    }
}

// ---------------------------------------------------------------------------
extern "C" void kernel_launch(void* const* d_in, const int* in_sizes, int n_in,
                              void* d_out, int out_size) {
    const float* x = (const float*)d_in[0];  // (2048, 2048)
    const float* w = (const float*)d_in[1];  // (16, 8192)
    const float* c = (const float*)d_in[2];  // (2048, 8192, 2)
    float* out = (float*)d_out;              // (2048, 8192)

    cudaFuncSetAttribute(k_gemm, cudaFuncAttributeMaxDynamicSharedMemorySize, DYN_SMEM);

    k_prep<<<(BATCH * NIN) / 256 + NG / 256, 256>>>(x, w);
    k_exp_t<<<dim3(NCOL / 32, NIN / 256), 256>>>(c);
    k_rs<<<NCOL / 256, 256>>>();
    k_gemm<<<dim3(NCOL / BN, BATCH / BM), 512, DYN_SMEM>>>(out);
}

// round 8
// speedup vs baseline: 1.7809x; 1.0391x over previous
#include <cuda_runtime.h>
#include <cuda_bf16.h>
#include <cstdint>

#define BATCH 2048
#define NIN   2048
#define NG    8192
#define NCOL  16384  // NG*2

// ---------------------------------------------------------------------------
// Scratch (static device globals -- allocation-free rule)
__device__ __align__(1024) __nv_bfloat16 g_Pt[(size_t)NCOL * NIN];  // exp(c)^T, 67 MB
__device__ __align__(1024) __nv_bfloat16 g_xb[(size_t)BATCH * NIN]; // x bf16, 8 MB
__device__ float  g_spart[8 * NCOL];
__device__ float  g_rs[NCOL];
__device__ float4 g_coef4[NG];     // (alpha, beta, gamma, delta) per gate

__device__ __forceinline__ uint32_t smem_to_u32(const void* p) {
    uint32_t a;
    asm("{ .reg .u64 t; cvta.to.shared.u64 t, %1; cvt.u32.u64 %0, t; }" : "=r"(a) : "l"(p));
    return a;
}

// ---------------------------------------------------------------------------
// Kernel 1: fused x->bf16 cast + gate coefficient precompute.
__global__ __launch_bounds__(256) void k_prep(const float* __restrict__ x,
                                              const float* __restrict__ w) {
    int b = blockIdx.x;
    if (b < (BATCH * NIN) / 256) {
        int i = b * 256 + threadIdx.x;
        g_xb[i] = __float2bfloat16(x[i]);
        return;
    }
    int g = (b - (BATCH * NIN) / 256) * 256 + threadIdx.x;
    if (g >= NG) return;
    float v[16];
    float m = -1e30f;
#pragma unroll
    for (int k = 0; k < 16; ++k) { v[k] = w[k * NG + g]; m = fmaxf(m, v[k]); }
    float sum = 0.f;
#pragma unroll
    for (int k = 0; k < 16; ++k) { v[k] = __expf(v[k] - m); sum += v[k]; }
    float inv = 1.f / sum;
#pragma unroll
    for (int k = 0; k < 16; ++k) v[k] *= inv;

    float al = v[8]+v[9]+v[10]+v[11]+v[12]+v[13]+v[14]+v[15];
    float be = v[2]+v[3]+v[6]+v[7] - v[8]-v[9]-v[12]-v[13];
    float ga = v[4]+v[5]+v[6]+v[7] - v[8]-v[9]-v[10]-v[11];
    float de = v[1]-v[2]-v[4]-2.f*v[6]-v[7]+v[8]+2.f*v[9]+v[11]+v[13]-v[14];
    g_coef4[g] = make_float4(al, be, ga, de);
}

// ---------------------------------------------------------------------------
// Kernel 2: Pt[j, i] = exp(c[i, j]) (bf16, transposed) + partial column sums.
__global__ __launch_bounds__(256) void k_exp_t(const float* __restrict__ c) {
    __shared__ __nv_bfloat16 sm[256][34];
    __shared__ float ssum[8][32];
    const int tj = threadIdx.x & 31;
    const int ti = threadIdx.x >> 5;
    const int j0 = blockIdx.x * 32;
    const int i0 = blockIdx.y * 256;

    float s = 0.f;
#pragma unroll 4
    for (int it = 0; it < 32; ++it) {
        int il = ti + 8 * it;
        float e = __expf(c[(size_t)(i0 + il) * NCOL + j0 + tj]);
        sm[il][tj] = __float2bfloat16(e);
        s += e;
    }
    ssum[ti][tj] = s;
    __syncthreads();
    if (ti == 0) {
        float t = 0.f;
#pragma unroll
        for (int k = 0; k < 8; ++k) t += ssum[k][tj];
        g_spart[blockIdx.y * NCOL + j0 + tj] = t;
    }
#pragma unroll 4
    for (int jj = 0; jj < 32; ++jj) {
        g_Pt[(size_t)(j0 + jj) * NIN + i0 + threadIdx.x] = sm[threadIdx.x][jj];
    }
}

// Kernel 3: reduce partials -> reciprocal column sums
__global__ void k_rs() {
    int j = blockIdx.x * 256 + threadIdx.x;
    float s = 0.f;
#pragma unroll
    for (int k = 0; k < 8; ++k) s += g_spart[k * NCOL + j];
    g_rs[j] = 1.f / s;
}

// ---------------------------------------------------------------------------
// Kernel 4: mma.sync bf16 GEMM  y = xb @ Pt^T  with fused gate epilogue.
// CTA tile 128x128, BK=32, 4-stage cp.async pipeline, 256 threads = 8 warps
// (2 in M x 4 in N), warp tile 64x32. 2 CTAs/SM to fill tensor-pipe bubbles.
#define BM 128
#define BN 128
#define BK 32
#define STAGES 4
#define LDSB 80                       // smem row stride in bytes (40 bf16)
#define A_BYTES (BM * LDSB)           // 10240
#define B_BYTES (BN * LDSB)           // 10240
#define STG (A_BYTES + B_BYTES)       // 20480
#define DYN_SMEM (STAGES * STG)       // 81920 (x2 CTAs = 160KB/SM)
#define NKT (NIN / BK)                // 64

#define CP_ASYNC(dst, src) \
    asm volatile("cp.async.cg.shared.global [%0], [%1], 16;" :: "r"(dst), "l"(src) : "memory")
#define CP_COMMIT() asm volatile("cp.async.commit_group;" ::: "memory")
#define CP_WAIT2()  asm volatile("cp.async.wait_group 2;" ::: "memory")

__device__ __forceinline__ void ldsm4(uint32_t& r0, uint32_t& r1, uint32_t& r2, uint32_t& r3, uint32_t a) {
    asm volatile("ldmatrix.sync.aligned.m8n8.x4.shared.b16 {%0,%1,%2,%3}, [%4];"
                 : "=r"(r0), "=r"(r1), "=r"(r2), "=r"(r3) : "r"(a));
}
__device__ __forceinline__ void mma16816(float* d, uint32_t a0, uint32_t a1, uint32_t a2, uint32_t a3,
                                         uint32_t b0, uint32_t b1) {
    asm volatile("mma.sync.aligned.m16n8k16.row.col.f32.bf16.bf16.f32 "
                 "{%0,%1,%2,%3}, {%4,%5,%6,%7}, {%8,%9}, {%0,%1,%2,%3};"
                 : "+f"(d[0]), "+f"(d[1]), "+f"(d[2]), "+f"(d[3])
                 : "r"(a0), "r"(a1), "r"(a2), "r"(a3), "r"(b0), "r"(b1));
}

__global__ __launch_bounds__(256, 2) void k_gemm(float* __restrict__ out) {
    extern __shared__ __align__(128) unsigned char dynsm[];
    const uint32_t sbase = smem_to_u32(dynsm);

    const int tid = threadIdx.x;
    const int wid = tid >> 5, lane = tid & 31;
    const int wm = wid >> 2, wn = wid & 3;      // 2x4 warp grid, warp tile 64x32
    const int bn = blockIdx.x, bm = blockIdx.y;

    // load mapping: A/B each 128 rows x 64B -> 2 chunks of 16B per thread each
    const int ar = tid >> 2, ac = tid & 3;       // ar 0..63, ac 0..3 (x8 bf16)
    const __nv_bfloat16* gA = g_xb + (size_t)(bm * BM + ar) * NIN + ac * 8;
    const __nv_bfloat16* gB = g_Pt + (size_t)(bn * BN + ar) * NIN + ac * 8;

    float acc[4][4][4];
#pragma unroll
    for (int mi = 0; mi < 4; ++mi)
#pragma unroll
        for (int ni = 0; ni < 4; ++ni)
#pragma unroll
            for (int q = 0; q < 4; ++q) acc[mi][ni][q] = 0.f;

    auto load_stage = [&](int s, int t) {
        const uint32_t sa = sbase + s * STG;
        const uint32_t sb = sa + A_BYTES;
        const int koff = t * BK;
#pragma unroll
        for (int i = 0; i < 2; ++i) {
            CP_ASYNC(sa + (ar + i * 64) * LDSB + ac * 16, gA + (size_t)(i * 64) * NIN + koff);
            CP_ASYNC(sb + (ar + i * 64) * LDSB + ac * 16, gB + (size_t)(i * 64) * NIN + koff);
        }
    };

#pragma unroll
    for (int s = 0; s < STAGES - 1; ++s) { load_stage(s, s); CP_COMMIT(); }
    CP_WAIT2();
    __syncthreads();

    const uint32_t aLaneOff = (uint32_t)((lane & 15) * LDSB + (lane >> 4) * 16);
    const uint32_t bLaneOff = (uint32_t)(((lane & 7) + ((lane >> 4) << 3)) * LDSB + ((lane >> 3) & 1) * 16);

#pragma unroll 4
    for (int t = 0; t < NKT; ++t) {
        if (t + STAGES - 1 < NKT) load_stage((t + STAGES - 1) % STAGES, t + STAGES - 1);
        CP_COMMIT();

        const uint32_t sa = sbase + (t % STAGES) * STG + (uint32_t)(wm * 64) * LDSB;
        const uint32_t sb = sbase + (t % STAGES) * STG + A_BYTES + (uint32_t)(wn * 32) * LDSB;

#pragma unroll
        for (int kk = 0; kk < 2; ++kk) {
            uint32_t a[4][4], b[2][4];
#pragma unroll
            for (int mi = 0; mi < 4; ++mi)
                ldsm4(a[mi][0], a[mi][1], a[mi][2], a[mi][3],
                      sa + (uint32_t)(mi * 16) * LDSB + kk * 32 + aLaneOff);
#pragma unroll
            for (int nj = 0; nj < 2; ++nj)
                ldsm4(b[nj][0], b[nj][1], b[nj][2], b[nj][3],
                      sb + (uint32_t)(nj * 16) * LDSB + kk * 32 + bLaneOff);
#pragma unroll
            for (int mi = 0; mi < 4; ++mi)
#pragma unroll
                for (int nj = 0; nj < 2; ++nj) {
                    mma16816(acc[mi][2 * nj],     a[mi][0], a[mi][1], a[mi][2], a[mi][3], b[nj][0], b[nj][1]);
                    mma16816(acc[mi][2 * nj + 1], a[mi][0], a[mi][1], a[mi][2], a[mi][3], b[nj][2], b[nj][3]);
                }
        }
        CP_WAIT2();
        __syncthreads();
    }

    // ------------------------------------------------------------------
    // Epilogue in registers. Even col = A, odd col = B of gate g.
    const int row0 = bm * BM + wm * 64 + (lane >> 2);
    const int gbase = bn * (BN / 2) + wn * 16 + (lane & 3);
#pragma unroll
    for (int ni = 0; ni < 4; ++ni) {
        const int g = gbase + ni * 4;
        const float2 rsv = *(const float2*)(g_rs + 2 * g);
        const float4 cf = g_coef4[g];
#pragma unroll
        for (int mi = 0; mi < 4; ++mi) {
            const float* d = acc[mi][ni];
            float Av = d[0] * rsv.x, Bv = d[1] * rsv.y;
            out[(size_t)(row0 + mi * 16) * NG + g] =
                cf.x + cf.y * Av + cf.z * Bv + cf.w * (Av * Bv);
            Av = d[2] * rsv.x; Bv = d[3] * rsv.y;
            out[(size_t)(row0 + mi * 16 + 8) * NG + g] =
                cf.x + cf.y * Av + cf.z * Bv + cf.w * (Av * Bv);
        }
    }
}

// ---------------------------------------------------------------------------
extern "C" void kernel_launch(void* const* d_in, const int* in_sizes, int n_in,
                              void* d_out, int out_size) {
    const float* x = (const float*)d_in[0];  // (2048, 2048)
    const float* w = (const float*)d_in[1];  // (16, 8192)
    const float* c = (const float*)d_in[2];  // (2048, 8192, 2)
    float* out = (float*)d_out;              // (2048, 8192)

    cudaFuncSetAttribute(k_gemm, cudaFuncAttributeMaxDynamicSharedMemorySize, DYN_SMEM);

    k_prep<<<(BATCH * NIN) / 256 + NG / 256, 256>>>(x, w);
    k_exp_t<<<dim3(NCOL / 32, NIN / 256), 256>>>(c);
    k_rs<<<NCOL / 256, 256>>>();
    k_gemm<<<dim3(NCOL / BN, BATCH / BM), 256, DYN_SMEM>>>(out);
}

// round 9
// speedup vs baseline: 1.8632x; 1.0462x over previous
#include <cuda_runtime.h>
#include <cuda_bf16.h>
#include <cstdint>

#define BATCH 2048
#define NIN   2048
#define NG    8192
#define NCOL  16384  // NG*2

// ---------------------------------------------------------------------------
// Scratch (static device globals -- allocation-free rule)
__device__ __align__(1024) __nv_bfloat16 g_Pt[(size_t)NCOL * NIN];  // exp(c)^T, 67 MB
__device__ __align__(1024) __nv_bfloat16 g_xb[(size_t)BATCH * NIN]; // x bf16, 8 MB
__device__ float  g_spart[8 * NCOL];
__device__ float  g_rs[NCOL];
__device__ float4 g_coef4[NG];     // (alpha, beta, gamma, delta) per gate

__device__ __forceinline__ uint32_t smem_to_u32(const void* p) {
    uint32_t a;
    asm("{ .reg .u64 t; cvta.to.shared.u64 t, %1; cvt.u32.u64 %0, t; }" : "=r"(a) : "l"(p));
    return a;
}

// ---------------------------------------------------------------------------
// Kernel 1: fused x->bf16 cast + gate coefficient precompute.
__global__ __launch_bounds__(256) void k_prep(const float* __restrict__ x,
                                              const float* __restrict__ w) {
    int b = blockIdx.x;
    if (b < (BATCH * NIN) / 256) {
        int i = b * 256 + threadIdx.x;
        g_xb[i] = __float2bfloat16(x[i]);
        return;
    }
    int g = (b - (BATCH * NIN) / 256) * 256 + threadIdx.x;
    if (g >= NG) return;
    float v[16];
    float m = -1e30f;
#pragma unroll
    for (int k = 0; k < 16; ++k) { v[k] = w[k * NG + g]; m = fmaxf(m, v[k]); }
    float sum = 0.f;
#pragma unroll
    for (int k = 0; k < 16; ++k) { v[k] = __expf(v[k] - m); sum += v[k]; }
    float inv = 1.f / sum;
#pragma unroll
    for (int k = 0; k < 16; ++k) v[k] *= inv;

    float al = v[8]+v[9]+v[10]+v[11]+v[12]+v[13]+v[14]+v[15];
    float be = v[2]+v[3]+v[6]+v[7] - v[8]-v[9]-v[12]-v[13];
    float ga = v[4]+v[5]+v[6]+v[7] - v[8]-v[9]-v[10]-v[11];
    float de = v[1]-v[2]-v[4]-2.f*v[6]-v[7]+v[8]+2.f*v[9]+v[11]+v[13]-v[14];
    g_coef4[g] = make_float4(al, be, ga, de);
}

// ---------------------------------------------------------------------------
// Kernel 2: Pt[j, i] = exp(c[i, j]) (bf16, transposed) + partial column sums.
__global__ __launch_bounds__(256) void k_exp_t(const float* __restrict__ c) {
    __shared__ __nv_bfloat16 sm[256][34];
    __shared__ float ssum[8][32];
    const int tj = threadIdx.x & 31;
    const int ti = threadIdx.x >> 5;
    const int j0 = blockIdx.x * 32;
    const int i0 = blockIdx.y * 256;

    float s = 0.f;
#pragma unroll 4
    for (int it = 0; it < 32; ++it) {
        int il = ti + 8 * it;
        float e = __expf(c[(size_t)(i0 + il) * NCOL + j0 + tj]);
        sm[il][tj] = __float2bfloat16(e);
        s += e;
    }
    ssum[ti][tj] = s;
    __syncthreads();
    if (ti == 0) {
        float t = 0.f;
#pragma unroll
        for (int k = 0; k < 8; ++k) t += ssum[k][tj];
        g_spart[blockIdx.y * NCOL + j0 + tj] = t;
    }
#pragma unroll 4
    for (int jj = 0; jj < 32; ++jj) {
        g_Pt[(size_t)(j0 + jj) * NIN + i0 + threadIdx.x] = sm[threadIdx.x][jj];
    }
}

// Kernel 3: reduce partials -> reciprocal column sums
__global__ void k_rs() {
    int j = blockIdx.x * 256 + threadIdx.x;
    float s = 0.f;
#pragma unroll
    for (int k = 0; k < 8; ++k) s += g_spart[k * NCOL + j];
    g_rs[j] = 1.f / s;
}

// ---------------------------------------------------------------------------
// Kernel 4: mma.sync bf16 GEMM  y = xb @ Pt^T  with fused gate epilogue.
// CTA tile 128x128, BK=32, 4-stage cp.async pipeline, 128 threads = 4 warps
// (2x2 grid), warp tile 64x64 -> minimal LDSM redundancy (x2 A, x2 B).
// 2 CTAs/SM.
#define BM 128
#define BN 128
#define BK 32
#define STAGES 4
#define LDSB 80                       // smem row stride in bytes (40 bf16)
#define A_BYTES (BM * LDSB)           // 10240
#define B_BYTES (BN * LDSB)           // 10240
#define STG (A_BYTES + B_BYTES)       // 20480
#define DYN_SMEM (STAGES * STG)       // 81920 (x2 CTAs = 160KB/SM)
#define NKT (NIN / BK)                // 64

#define CP_ASYNC(dst, src) \
    asm volatile("cp.async.cg.shared.global [%0], [%1], 16;" :: "r"(dst), "l"(src) : "memory")
#define CP_COMMIT() asm volatile("cp.async.commit_group;" ::: "memory")
#define CP_WAIT2()  asm volatile("cp.async.wait_group 2;" ::: "memory")

__device__ __forceinline__ void ldsm4(uint32_t& r0, uint32_t& r1, uint32_t& r2, uint32_t& r3, uint32_t a) {
    asm volatile("ldmatrix.sync.aligned.m8n8.x4.shared.b16 {%0,%1,%2,%3}, [%4];"
                 : "=r"(r0), "=r"(r1), "=r"(r2), "=r"(r3) : "r"(a));
}
__device__ __forceinline__ void mma16816(float* d, uint32_t a0, uint32_t a1, uint32_t a2, uint32_t a3,
                                         uint32_t b0, uint32_t b1) {
    asm volatile("mma.sync.aligned.m16n8k16.row.col.f32.bf16.bf16.f32 "
                 "{%0,%1,%2,%3}, {%4,%5,%6,%7}, {%8,%9}, {%0,%1,%2,%3};"
                 : "+f"(d[0]), "+f"(d[1]), "+f"(d[2]), "+f"(d[3])
                 : "r"(a0), "r"(a1), "r"(a2), "r"(a3), "r"(b0), "r"(b1));
}

__global__ __launch_bounds__(128, 2) void k_gemm(float* __restrict__ out) {
    extern __shared__ __align__(128) unsigned char dynsm[];
    const uint32_t sbase = smem_to_u32(dynsm);

    const int tid = threadIdx.x;
    const int wid = tid >> 5, lane = tid & 31;
    const int wm = wid >> 1, wn = wid & 1;      // 2x2 warp grid, warp tile 64x64
    const int bn = blockIdx.x, bm = blockIdx.y;

    // load mapping: tile 128 rows x 64B = 512 chunks of 16B; 4 chunks/thread each tile
    const int ar = tid >> 2, ac = tid & 3;       // ar 0..31, ac 0..3
    const __nv_bfloat16* gA = g_xb + (size_t)(bm * BM + ar) * NIN + ac * 8;
    const __nv_bfloat16* gB = g_Pt + (size_t)(bn * BN + ar) * NIN + ac * 8;

    float acc[4][8][4];
#pragma unroll
    for (int mi = 0; mi < 4; ++mi)
#pragma unroll
        for (int ni = 0; ni < 8; ++ni)
#pragma unroll
            for (int q = 0; q < 4; ++q) acc[mi][ni][q] = 0.f;

    auto load_stage = [&](int s, int t) {
        const uint32_t sa = sbase + s * STG;
        const uint32_t sb = sa + A_BYTES;
        const int koff = t * BK;
#pragma unroll
        for (int i = 0; i < 4; ++i) {
            CP_ASYNC(sa + (ar + i * 32) * LDSB + ac * 16, gA + (size_t)(i * 32) * NIN + koff);
            CP_ASYNC(sb + (ar + i * 32) * LDSB + ac * 16, gB + (size_t)(i * 32) * NIN + koff);
        }
    };

#pragma unroll
    for (int s = 0; s < STAGES - 1; ++s) { load_stage(s, s); CP_COMMIT(); }
    CP_WAIT2();
    __syncthreads();

    const uint32_t aLaneOff = (uint32_t)((lane & 15) * LDSB + (lane >> 4) * 16);
    const uint32_t bLaneOff = (uint32_t)(((lane & 7) + ((lane >> 4) << 3)) * LDSB + ((lane >> 3) & 1) * 16);

#pragma unroll 4
    for (int t = 0; t < NKT; ++t) {
        if (t + STAGES - 1 < NKT) load_stage((t + STAGES - 1) % STAGES, t + STAGES - 1);
        CP_COMMIT();

        const uint32_t sa = sbase + (t % STAGES) * STG + (uint32_t)(wm * 64) * LDSB;
        const uint32_t sb = sbase + (t % STAGES) * STG + A_BYTES + (uint32_t)(wn * 64) * LDSB;

        // Batch all fragment loads for this k-tile (16 LDSM, high MLP)...
        uint32_t a[2][4][4], b[2][4][4];
#pragma unroll
        for (int kk = 0; kk < 2; ++kk) {
#pragma unroll
            for (int mi = 0; mi < 4; ++mi)
                ldsm4(a[kk][mi][0], a[kk][mi][1], a[kk][mi][2], a[kk][mi][3],
                      sa + (uint32_t)(mi * 16) * LDSB + kk * 32 + aLaneOff);
#pragma unroll
            for (int nj = 0; nj < 4; ++nj)
                ldsm4(b[kk][nj][0], b[kk][nj][1], b[kk][nj][2], b[kk][nj][3],
                      sb + (uint32_t)(nj * 16) * LDSB + kk * 32 + bLaneOff);
        }
        // ...then a long uninterrupted MMA burst (64 HMMA).
#pragma unroll
        for (int kk = 0; kk < 2; ++kk)
#pragma unroll
            for (int mi = 0; mi < 4; ++mi)
#pragma unroll
                for (int nj = 0; nj < 4; ++nj) {
                    mma16816(acc[mi][2 * nj],     a[kk][mi][0], a[kk][mi][1], a[kk][mi][2], a[kk][mi][3],
                             b[kk][nj][0], b[kk][nj][1]);
                    mma16816(acc[mi][2 * nj + 1], a[kk][mi][0], a[kk][mi][1], a[kk][mi][2], a[kk][mi][3],
                             b[kk][nj][2], b[kk][nj][3]);
                }
        CP_WAIT2();
        __syncthreads();
    }

    // ------------------------------------------------------------------
    // Epilogue in registers. Even col = A, odd col = B of gate g.
    const int row0 = bm * BM + wm * 64 + (lane >> 2);
    const int gbase = bn * (BN / 2) + wn * 32 + (lane & 3);
#pragma unroll
    for (int ni = 0; ni < 8; ++ni) {
        const int g = gbase + ni * 4;
        const float2 rsv = *(const float2*)(g_rs + 2 * g);
        const float4 cf = g_coef4[g];
#pragma unroll
        for (int mi = 0; mi < 4; ++mi) {
            const float* d = acc[mi][ni];
            float Av = d[0] * rsv.x, Bv = d[1] * rsv.y;
            out[(size_t)(row0 + mi * 16) * NG + g] =
                cf.x + cf.y * Av + cf.z * Bv + cf.w * (Av * Bv);
            Av = d[2] * rsv.x; Bv = d[3] * rsv.y;
            out[(size_t)(row0 + mi * 16 + 8) * NG + g] =
                cf.x + cf.y * Av + cf.z * Bv + cf.w * (Av * Bv);
        }
    }
}

// ---------------------------------------------------------------------------
extern "C" void kernel_launch(void* const* d_in, const int* in_sizes, int n_in,
                              void* d_out, int out_size) {
    const float* x = (const float*)d_in[0];  // (2048, 2048)
    const float* w = (const float*)d_in[1];  // (16, 8192)
    const float* c = (const float*)d_in[2];  // (2048, 8192, 2)
    float* out = (float*)d_out;              // (2048, 8192)

    cudaFuncSetAttribute(k_gemm, cudaFuncAttributeMaxDynamicSharedMemorySize, DYN_SMEM);

    k_prep<<<(BATCH * NIN) / 256 + NG / 256, 256>>>(x, w);
    k_exp_t<<<dim3(NCOL / 32, NIN / 256), 256>>>(c);
    k_rs<<<NCOL / 256, 256>>>();
    k_gemm<<<dim3(NCOL / BN, BATCH / BM), 128, DYN_SMEM>>>(out);
}